// round 1
// baseline (speedup 1.0000x reference)
#include <cuda_runtime.h>
#include <math.h>

#define NB    8
#define DIM   768
#define MID   96
#define HWP   4096
#define NPIX  32768
#define NTAP  49

// ---------------- scratch (static device globals; no runtime allocation) ----
__device__ float g_xemb[NPIX * MID];
__device__ float g_temb[NPIX * MID];
__device__ float g_y[NPIX * MID];
__device__ float g_common[NPIX * MID];
__device__ float g_fds[NPIX * MID];
__device__ float g_gvec[NB * MID];
__device__ float g_dyn[NB * NTAP * MID];

// ============================================================================
// Kernel 1: fused LayerNorm + down Linear (768 -> 96) for x and t.
// Tile: 128 pixels x 96 outputs, 256 threads, 8x6 register micro-tile.
// Two-pass LN: pass 1 computes per-row mean/rstd; pass 2 stages normalized
// K-chunks of 32 into smem alongside the weight chunk.
// ============================================================================
__global__ void __launch_bounds__(256, 2) k_ln_down(
    const float* __restrict__ x, const float* __restrict__ t,
    const float* __restrict__ lnw0, const float* __restrict__ lnb0,
    const float* __restrict__ dw0,  const float* __restrict__ db0,
    const float* __restrict__ lnw1, const float* __restrict__ lnb1,
    const float* __restrict__ dw1,  const float* __restrict__ db1)
{
    const int which = blockIdx.y;
    const float* __restrict__ in   = which ? t    : x;
    const float* __restrict__ lnw  = which ? lnw1 : lnw0;
    const float* __restrict__ lnb  = which ? lnb1 : lnb0;
    const float* __restrict__ W    = which ? dw1  : dw0;
    const float* __restrict__ bias = which ? db1  : db0;
    float* __restrict__ out = which ? g_temb : g_xemb;

    __shared__ float s_mean[128], s_rstd[128];
    __shared__ float As[32][132];   // [k within chunk][pixel], pad 132
    __shared__ float Bs[32][97];    // [k within chunk][out col], pad 97

    const int tid  = threadIdx.x;
    const int warp = tid >> 5, lane = tid & 31;
    const int base = blockIdx.x * 128;

    // ---- pass 1: LN statistics (one warp handles 16 rows)
    for (int rr = 0; rr < 16; rr++) {
        int r = warp * 16 + rr;
        const float4* rp = reinterpret_cast<const float4*>(in + (base + r) * DIM);
        float s = 0.f, sq = 0.f;
        #pragma unroll
        for (int it = 0; it < 6; it++) {
            float4 v = rp[lane + 32 * it];
            s  += v.x + v.y + v.z + v.w;
            sq += v.x * v.x + v.y * v.y + v.z * v.z + v.w * v.w;
        }
        #pragma unroll
        for (int o = 16; o > 0; o >>= 1) {
            s  += __shfl_xor_sync(0xffffffffu, s,  o);
            sq += __shfl_xor_sync(0xffffffffu, sq, o);
        }
        if (lane == 0) {
            float m   = s * (1.f / 768.f);
            float var = sq * (1.f / 768.f) - m * m;
            s_mean[r] = m;
            s_rstd[r] = rsqrtf(var + 1e-6f);
        }
    }
    __syncthreads();

    const int ty = tid >> 4, tx = tid & 15;
    const int cS = tid & 31, r0 = tid >> 5;

    float acc[8][6];
    #pragma unroll
    for (int i = 0; i < 8; i++)
        #pragma unroll
        for (int u = 0; u < 6; u++) acc[i][u] = 0.f;

    for (int k0 = 0; k0 < DIM; k0 += 32) {
        const float lw = lnw[k0 + cS], lb = lnb[k0 + cS];
        #pragma unroll
        for (int rr = 0; rr < 16; rr++) {
            int r = r0 + rr * 8;
            float v = in[(base + r) * DIM + k0 + cS];
            As[cS][r] = (v - s_mean[r]) * s_rstd[r] * lw + lb;
        }
        #pragma unroll
        for (int jj = 0; jj < 12; jj++) {
            int j = r0 + jj * 8;
            Bs[cS][j] = W[j * DIM + k0 + cS];
        }
        __syncthreads();
        #pragma unroll
        for (int kk = 0; kk < 32; kk++) {
            float4 a0 = *reinterpret_cast<const float4*>(&As[kk][ty * 8]);
            float4 a1 = *reinterpret_cast<const float4*>(&As[kk][ty * 8 + 4]);
            float av[8] = {a0.x, a0.y, a0.z, a0.w, a1.x, a1.y, a1.z, a1.w};
            float bv[6];
            #pragma unroll
            for (int u = 0; u < 6; u++) bv[u] = Bs[kk][tx + 16 * u];
            #pragma unroll
            for (int i = 0; i < 8; i++)
                #pragma unroll
                for (int u = 0; u < 6; u++)
                    acc[i][u] = fmaf(av[i], bv[u], acc[i][u]);
        }
        __syncthreads();
    }

    #pragma unroll
    for (int i = 0; i < 8; i++) {
        int row = base + ty * 8 + i;
        #pragma unroll
        for (int u = 0; u < 6; u++) {
            int c = tx + 16 * u;
            out[row * MID + c] = acc[i][u] + bias[c];
        }
    }
}

// ============================================================================
// Kernel 2: gvec[b][c] = mean over 4096 pixels of x_emb. Deterministic tree.
// grid = NB*MID blocks, 256 threads.
// ============================================================================
__global__ void __launch_bounds__(256) k_gvec()
{
    int b = blockIdx.x / MID, c = blockIdx.x % MID;
    const float* p = g_xemb + (b * HWP) * MID + c;
    float s = 0.f;
    for (int i = threadIdx.x; i < HWP; i += 256) s += p[i * MID];
    __shared__ float red[256];
    red[threadIdx.x] = s;
    __syncthreads();
    for (int o = 128; o > 0; o >>= 1) {
        if (threadIdx.x < o) red[threadIdx.x] += red[threadIdx.x + o];
        __syncthreads();
    }
    if (threadIdx.x == 0) g_gvec[b * MID + c] = red[0] * (1.f / 4096.f);
}

// ============================================================================
// Kernel 3: FDS MLP + dynamic kernel. One block per batch.
// dyn stored as [B][49 taps][96 channels] for vectorized conv reads.
// ============================================================================
__global__ void __launch_bounds__(256) k_mlp(
    const float* __restrict__ m1w, const float* __restrict__ m1b,
    const float* __restrict__ m2w, const float* __restrict__ m2b,
    const float* __restrict__ basis)
{
    int b = blockIdx.x;
    int tid = threadIdx.x;
    __shared__ float gs[MID];
    __shared__ float hid[24];
    __shared__ float wsm[4];

    if (tid < MID) gs[tid] = g_gvec[b * MID + tid];
    __syncthreads();
    if (tid < 24) {
        float a = m1b[tid];
        for (int c = 0; c < MID; c++) a = fmaf(gs[c], m1w[tid * MID + c], a);
        hid[tid] = fmaxf(a, 0.f);
    }
    __syncthreads();
    if (tid < 4) {
        float a = m2b[tid];
        for (int h = 0; h < 24; h++) a = fmaf(hid[h], m2w[tid * 24 + h], a);
        wsm[tid] = a;
    }
    __syncthreads();
    if (tid == 0) {
        float mx = fmaxf(fmaxf(wsm[0], wsm[1]), fmaxf(wsm[2], wsm[3]));
        float e0 = expf(wsm[0] - mx), e1 = expf(wsm[1] - mx);
        float e2 = expf(wsm[2] - mx), e3 = expf(wsm[3] - mx);
        float inv = 1.f / (e0 + e1 + e2 + e3);
        wsm[0] = e0 * inv; wsm[1] = e1 * inv; wsm[2] = e2 * inv; wsm[3] = e3 * inv;
    }
    __syncthreads();
    for (int i = tid; i < MID * NTAP; i += 256) {
        int c = i / NTAP, tj = i % NTAP;
        float v = 0.f;
        #pragma unroll
        for (int k = 0; k < 4; k++)
            v = fmaf(wsm[k], basis[(k * MID + c) * NTAP + tj], v);
        g_dyn[(b * NTAP + tj) * MID + c] = v;
    }
}

// ============================================================================
// Kernel 4: depthwise 3x3 conv (zero pad) + bias + SiLU on t_emb.
// One thread per (pixel, 4-channel group), float4 loads/stores.
// ============================================================================
__global__ void __launch_bounds__(256) k_dw(
    const float* __restrict__ dww, const float* __restrict__ dwb)
{
    int idx = blockIdx.x * 256 + threadIdx.x;       // NPIX * 24 total
    int c4 = idx % 24;
    int p  = (idx / 24) & (HWP - 1);
    int b  = idx / (24 * HWP);
    int c  = c4 * 4;
    int i = p >> 6, j = p & 63;

    float4 acc = make_float4(0.f, 0.f, 0.f, 0.f);
    #pragma unroll
    for (int kh = 0; kh < 3; kh++) {
        int ni = i + kh - 1;
        if ((unsigned)ni >= 64u) continue;
        #pragma unroll
        for (int kw = 0; kw < 3; kw++) {
            int nj = j + kw - 1;
            if ((unsigned)nj >= 64u) continue;
            float4 v = *reinterpret_cast<const float4*>(
                &g_temb[((b * HWP) + (ni << 6) + nj) * MID + c]);
            int wo = kh * 3 + kw;
            acc.x = fmaf(v.x, dww[(c + 0) * 9 + wo], acc.x);
            acc.y = fmaf(v.y, dww[(c + 1) * 9 + wo], acc.y);
            acc.z = fmaf(v.z, dww[(c + 2) * 9 + wo], acc.z);
            acc.w = fmaf(v.w, dww[(c + 3) * 9 + wo], acc.w);
        }
    }
    acc.x += dwb[c + 0]; acc.y += dwb[c + 1];
    acc.z += dwb[c + 2]; acc.w += dwb[c + 3];
    acc.x = acc.x / (1.f + expf(-acc.x));
    acc.y = acc.y / (1.f + expf(-acc.y));
    acc.z = acc.z / (1.f + expf(-acc.z));
    acc.w = acc.w / (1.f + expf(-acc.w));
    *reinterpret_cast<float4*>(&g_y[(b * HWP + p) * MID + c]) = acc;
}

// ============================================================================
// Kernel 5: style = 1x1 conv (96 -> 192) on y, fused with
// common = x_emb * (1 + gamma) + beta.  Tile 128 x 192, 512 threads, 8x6 micro.
// ============================================================================
__global__ void __launch_bounds__(512) k_style(
    const float* __restrict__ pww, const float* __restrict__ pwb)
{
    __shared__ float As[32][132];
    __shared__ float Bs[32][193];

    const int tid = threadIdx.x;
    const int base = blockIdx.x * 128;
    const int cS = tid & 31, r0 = tid >> 5;   // r0 0..15
    const int ty = tid >> 5, tx = tid & 31;

    float acc[8][6];
    #pragma unroll
    for (int i = 0; i < 8; i++)
        #pragma unroll
        for (int u = 0; u < 6; u++) acc[i][u] = 0.f;

    for (int k0 = 0; k0 < MID; k0 += 32) {
        #pragma unroll
        for (int rr = 0; rr < 8; rr++) {
            int r = r0 + rr * 16;
            As[cS][r] = g_y[(base + r) * MID + k0 + cS];
        }
        #pragma unroll
        for (int jj = 0; jj < 12; jj++) {
            int o = r0 + jj * 16;
            Bs[cS][o] = pww[o * MID + k0 + cS];
        }
        __syncthreads();
        #pragma unroll
        for (int kk = 0; kk < 32; kk++) {
            float4 a0 = *reinterpret_cast<const float4*>(&As[kk][ty * 8]);
            float4 a1 = *reinterpret_cast<const float4*>(&As[kk][ty * 8 + 4]);
            float av[8] = {a0.x, a0.y, a0.z, a0.w, a1.x, a1.y, a1.z, a1.w};
            float bv[6];
            #pragma unroll
            for (int u = 0; u < 6; u++) bv[u] = Bs[kk][tx + 32 * u];
            #pragma unroll
            for (int i = 0; i < 8; i++)
                #pragma unroll
                for (int u = 0; u < 6; u++)
                    acc[i][u] = fmaf(av[i], bv[u], acc[i][u]);
        }
        __syncthreads();
    }

    #pragma unroll
    for (int i = 0; i < 8; i++) {
        int row = base + ty * 8 + i;
        #pragma unroll
        for (int v = 0; v < 3; v++) {
            int c = tx + 32 * v;
            float gamma = acc[i][v]     + pwb[c];
            float beta  = acc[i][v + 3] + pwb[MID + c];
            float xe = g_xemb[row * MID + c];
            g_common[row * MID + c] = xe * (1.f + gamma) + beta;
        }
    }
}

// ============================================================================
// Kernel 6: FDS filtering. FFT product == circular conv with the 49-tap
// rolled kernel:  out[i,j] = sum_{a,d in [-3,3]} k[a+3,d+3] *
//                            common[(i-a)%64, (j-d)%64].
// Per-batch kernel staged in smem ([49][96] layout, float4 reads).
// Block: 384 threads = 24 channel-quads x 16 pixels.
// ============================================================================
__global__ void __launch_bounds__(384) k_fds()
{
    __shared__ float dyn_s[NTAP * MID];
    int bx = blockIdx.x;
    int b  = bx >> 8;
    int pb = (bx & 255) << 4;
    int tid = threadIdx.x;

    for (int i2 = tid; i2 < NTAP * MID; i2 += 384)
        dyn_s[i2] = g_dyn[b * NTAP * MID + i2];
    __syncthreads();

    int tx = tid % 24, ty = tid / 24;
    int p = pb + ty;
    int i = p >> 6, j = p & 63;
    int c = tx * 4;
    const float* cm = g_common + (b * HWP) * MID;

    float4 acc = make_float4(0.f, 0.f, 0.f, 0.f);
    #pragma unroll
    for (int a = -3; a <= 3; a++) {
        int ni = (i - a) & 63;
        #pragma unroll
        for (int d = -3; d <= 3; d++) {
            int nj = (j - d) & 63;
            float4 v = *reinterpret_cast<const float4*>(
                &cm[((ni << 6) + nj) * MID + c]);
            float4 tp = *reinterpret_cast<const float4*>(
                &dyn_s[((a + 3) * 7 + (d + 3)) * MID + c]);
            acc.x = fmaf(v.x, tp.x, acc.x);
            acc.y = fmaf(v.y, tp.y, acc.y);
            acc.z = fmaf(v.z, tp.z, acc.z);
            acc.w = fmaf(v.w, tp.w, acc.w);
        }
    }
    *reinterpret_cast<float4*>(&g_fds[(b * HWP + p) * MID + c]) = acc;
}

// ============================================================================
// Kernel 7: up Linear (96 -> 768) + bias + residual x.
// Tile 128 x 128, 256 threads, 8x8 micro-tile. grid.y covers 6 col blocks.
// ============================================================================
__global__ void __launch_bounds__(256, 2) k_up(
    const float* __restrict__ upw, const float* __restrict__ upb,
    const float* __restrict__ x, float* __restrict__ out)
{
    __shared__ float As[32][132];
    __shared__ float Bs[32][132];

    const int tid = threadIdx.x;
    const int base = blockIdx.x * 128;
    const int n0   = blockIdx.y * 128;
    const int cS = tid & 31, r0 = tid >> 5;   // r0 0..7
    const int ty = tid >> 4, tx = tid & 15;

    float acc[8][8];
    #pragma unroll
    for (int i = 0; i < 8; i++)
        #pragma unroll
        for (int u = 0; u < 8; u++) acc[i][u] = 0.f;

    for (int k0 = 0; k0 < MID; k0 += 32) {
        #pragma unroll
        for (int rr = 0; rr < 16; rr++) {
            int r = r0 * 16 + rr;
            As[cS][r] = g_fds[(base + r) * MID + k0 + cS];
            Bs[cS][r] = upw[(n0 + r) * MID + k0 + cS];
        }
        __syncthreads();
        #pragma unroll
        for (int kk = 0; kk < 32; kk++) {
            float4 a0 = *reinterpret_cast<const float4*>(&As[kk][ty * 8]);
            float4 a1 = *reinterpret_cast<const float4*>(&As[kk][ty * 8 + 4]);
            float4 b0 = *reinterpret_cast<const float4*>(&Bs[kk][tx * 8]);
            float4 b1 = *reinterpret_cast<const float4*>(&Bs[kk][tx * 8 + 4]);
            float av[8] = {a0.x, a0.y, a0.z, a0.w, a1.x, a1.y, a1.z, a1.w};
            float bv[8] = {b0.x, b0.y, b0.z, b0.w, b1.x, b1.y, b1.z, b1.w};
            #pragma unroll
            for (int i = 0; i < 8; i++)
                #pragma unroll
                for (int u = 0; u < 8; u++)
                    acc[i][u] = fmaf(av[i], bv[u], acc[i][u]);
        }
        __syncthreads();
    }

    #pragma unroll
    for (int i = 0; i < 8; i++) {
        int row = base + ty * 8 + i;
        #pragma unroll
        for (int q = 0; q < 2; q++) {
            int n = n0 + tx * 8 + q * 4;
            float4 xb = *reinterpret_cast<const float4*>(&x[row * DIM + n]);
            float4 bb = *reinterpret_cast<const float4*>(&upb[n]);
            float4 r;
            r.x = acc[i][q * 4 + 0] + bb.x + xb.x;
            r.y = acc[i][q * 4 + 1] + bb.y + xb.y;
            r.z = acc[i][q * 4 + 2] + bb.z + xb.z;
            r.w = acc[i][q * 4 + 3] + bb.w + xb.w;
            *reinterpret_cast<float4*>(&out[row * DIM + n]) = r;
        }
    }
}

// ============================================================================
extern "C" void kernel_launch(void* const* d_in, const int* in_sizes, int n_in,
                              void* d_out, int out_size)
{
    const float* x       = (const float*)d_in[0];
    const float* t       = (const float*)d_in[1];
    const float* ln_w    = (const float*)d_in[2];
    const float* ln_b    = (const float*)d_in[3];
    const float* down_w  = (const float*)d_in[4];
    const float* down_b  = (const float*)d_in[5];
    const float* ln1_w   = (const float*)d_in[6];
    const float* ln1_b   = (const float*)d_in[7];
    const float* down1_w = (const float*)d_in[8];
    const float* down1_b = (const float*)d_in[9];
    const float* dw_w    = (const float*)d_in[10];
    const float* dw_b    = (const float*)d_in[11];
    const float* pw_w    = (const float*)d_in[12];
    const float* pw_b    = (const float*)d_in[13];
    const float* mlp1_w  = (const float*)d_in[14];
    const float* mlp1_b  = (const float*)d_in[15];
    const float* mlp2_w  = (const float*)d_in[16];
    const float* mlp2_b  = (const float*)d_in[17];
    const float* basis   = (const float*)d_in[18];
    const float* up_w    = (const float*)d_in[19];
    const float* up_b    = (const float*)d_in[20];
    float* out = (float*)d_out;

    k_ln_down<<<dim3(NPIX / 128, 2), 256>>>(x, t, ln_w, ln_b, down_w, down_b,
                                            ln1_w, ln1_b, down1_w, down1_b);
    k_gvec<<<NB * MID, 256>>>();
    k_mlp<<<NB, 256>>>(mlp1_w, mlp1_b, mlp2_w, mlp2_b, basis);
    k_dw<<<NPIX * 24 / 256, 256>>>(dw_w, dw_b);
    k_style<<<NPIX / 128, 512>>>(pw_w, pw_b);
    k_fds<<<NB * (HWP / 16), 384>>>();
    k_up<<<dim3(NPIX / 128, DIM / 128), 256>>>(up_w, up_b, x, out);
}

// round 4
// speedup vs baseline: 1.5394x; 1.5394x over previous
#include <cuda_runtime.h>
#include <math.h>
#include <stdint.h>

#define NB    8
#define DIM   768
#define MID   96
#define HWP   4096
#define NPIX  32768
#define NTAP  49

// ---------------- scratch (static device globals) ---------------------------
__device__ float g_xemb[NPIX * MID];
__device__ float g_temb[NPIX * MID];
__device__ float g_y[NPIX * MID];
__device__ float g_common[NPIX * MID];
__device__ float g_fds[NPIX * MID];
__device__ float g_gvec[NB * MID];
__device__ float g_dyn[NB * NTAP * MID];

// ---------------- tf32 helpers ----------------------------------------------
// cvt.rna.tf32.f32 needs a .b32 destination (tf32 is carried in b32 regs).
__device__ __forceinline__ float to_tf32(float x) {
    uint32_t u;
    asm("cvt.rna.tf32.f32 %0, %1;" : "=r"(u) : "f"(x));
    return __uint_as_float(u);
}

#define MMA_TF32(d, a, b0, b1)                                                 \
    asm volatile(                                                              \
        "mma.sync.aligned.m16n8k8.row.col.f32.tf32.tf32.f32 "                  \
        "{%0,%1,%2,%3}, {%4,%5,%6,%7}, {%8,%9}, {%0,%1,%2,%3};"                \
        : "+f"((d)[0]), "+f"((d)[1]), "+f"((d)[2]), "+f"((d)[3])               \
        : "r"((a)[0]), "r"((a)[1]), "r"((a)[2]), "r"((a)[3]),                  \
          "r"(b0), "r"(b1))

// ============================================================================
// Kernel 1: fused LayerNorm + down Linear (768 -> 96), tf32 tensor cores.
// Tile 128 x 96, 256 threads (8 warps: 4 m-groups x 2 n-groups).
// Warp tile 32 x 48 (2 m16 tiles x 6 n8 tiles).
// ============================================================================
__global__ void __launch_bounds__(256, 2) k_ln_down(
    const float* __restrict__ x, const float* __restrict__ t,
    const float* __restrict__ lnw0, const float* __restrict__ lnb0,
    const float* __restrict__ dw0,  const float* __restrict__ db0,
    const float* __restrict__ lnw1, const float* __restrict__ lnb1,
    const float* __restrict__ dw1,  const float* __restrict__ db1)
{
    const int which = blockIdx.y;
    const float* __restrict__ in   = which ? t    : x;
    const float* __restrict__ lnw  = which ? lnw1 : lnw0;
    const float* __restrict__ lnb  = which ? lnb1 : lnb0;
    const float* __restrict__ W    = which ? dw1  : dw0;
    const float* __restrict__ bias = which ? db1  : db0;
    float* __restrict__ out = which ? g_temb : g_xemb;

    __shared__ float s_mean[128], s_rstd[128];
    __shared__ float As[128][36];
    __shared__ float Bs[96][36];

    const int tid  = threadIdx.x;
    const int warp = tid >> 5, lane = tid & 31;
    const int base = blockIdx.x * 128;

    // ---- pass 1: LN statistics (one warp handles 16 rows)
    for (int rr = 0; rr < 16; rr++) {
        int r = warp * 16 + rr;
        const float4* rp = reinterpret_cast<const float4*>(in + (base + r) * DIM);
        float s = 0.f, sq = 0.f;
        #pragma unroll
        for (int it = 0; it < 6; it++) {
            float4 v = rp[lane + 32 * it];
            s  += v.x + v.y + v.z + v.w;
            sq += v.x * v.x + v.y * v.y + v.z * v.z + v.w * v.w;
        }
        #pragma unroll
        for (int o = 16; o > 0; o >>= 1) {
            s  += __shfl_xor_sync(0xffffffffu, s,  o);
            sq += __shfl_xor_sync(0xffffffffu, sq, o);
        }
        if (lane == 0) {
            float m   = s * (1.f / 768.f);
            float var = sq * (1.f / 768.f) - m * m;
            s_mean[r] = m;
            s_rstd[r] = rsqrtf(var + 1e-6f);
        }
    }
    __syncthreads();

    const int gid = lane >> 2, ctid = lane & 3;
    const int wm = warp >> 1, wn = warp & 1;
    const int cS = tid & 31, rT = tid >> 5;

    float acc[2][6][4];
    #pragma unroll
    for (int i = 0; i < 2; i++)
        #pragma unroll
        for (int j = 0; j < 6; j++)
            #pragma unroll
            for (int q = 0; q < 4; q++) acc[i][j][q] = 0.f;

    for (int k0 = 0; k0 < DIM; k0 += 32) {
        const float lw = lnw[k0 + cS], lb = lnb[k0 + cS];
        #pragma unroll
        for (int rr = 0; rr < 16; rr++) {
            int r = rT + rr * 8;
            float v = in[(base + r) * DIM + k0 + cS];
            As[r][cS] = to_tf32((v - s_mean[r]) * s_rstd[r] * lw + lb);
        }
        #pragma unroll
        for (int jj = 0; jj < 12; jj++) {
            int j = rT + jj * 8;
            Bs[j][cS] = to_tf32(W[j * DIM + k0 + cS]);
        }
        __syncthreads();
        #pragma unroll
        for (int ks = 0; ks < 4; ks++) {
            const int k8 = ks * 8;
            uint32_t a[2][4];
            #pragma unroll
            for (int mt = 0; mt < 2; mt++) {
                int r = wm * 32 + mt * 16;
                a[mt][0] = __float_as_uint(As[r + gid    ][k8 + ctid]);
                a[mt][1] = __float_as_uint(As[r + gid + 8][k8 + ctid]);
                a[mt][2] = __float_as_uint(As[r + gid    ][k8 + ctid + 4]);
                a[mt][3] = __float_as_uint(As[r + gid + 8][k8 + ctid + 4]);
            }
            #pragma unroll
            for (int nt = 0; nt < 6; nt++) {
                int n = wn * 48 + nt * 8;
                uint32_t b0 = __float_as_uint(Bs[n + gid][k8 + ctid]);
                uint32_t b1 = __float_as_uint(Bs[n + gid][k8 + ctid + 4]);
                MMA_TF32(acc[0][nt], a[0], b0, b1);
                MMA_TF32(acc[1][nt], a[1], b0, b1);
            }
        }
        __syncthreads();
    }

    #pragma unroll
    for (int mt = 0; mt < 2; mt++) {
        int row0 = base + wm * 32 + mt * 16 + gid;
        #pragma unroll
        for (int nt = 0; nt < 6; nt++) {
            int c = wn * 48 + nt * 8 + 2 * ctid;
            float2 bb = make_float2(bias[c], bias[c + 1]);
            float2 r0v = make_float2(acc[mt][nt][0] + bb.x, acc[mt][nt][1] + bb.y);
            float2 r1v = make_float2(acc[mt][nt][2] + bb.x, acc[mt][nt][3] + bb.y);
            *reinterpret_cast<float2*>(&out[row0 * MID + c]) = r0v;
            *reinterpret_cast<float2*>(&out[(row0 + 8) * MID + c]) = r1v;
        }
    }
}

// ============================================================================
// Kernel 2: gvec = per-(b,c) mean over pixels, coalesced. grid=NB, 384 thr.
// ============================================================================
__global__ void __launch_bounds__(384) k_gvec()
{
    int b = blockIdx.x;
    int tid = threadIdx.x;
    int c = tid % MID, g = tid / MID;
    float s = 0.f;
    const float* p = g_xemb + (size_t)b * HWP * MID;
    for (int px = g; px < HWP; px += 4) s += p[px * MID + c];
    __shared__ float red[384];
    red[tid] = s;
    __syncthreads();
    if (tid < MID) {
        float tot = red[tid] + red[tid + 96] + red[tid + 192] + red[tid + 288];
        g_gvec[b * MID + tid] = tot * (1.f / 4096.f);
    }
}

// ============================================================================
// Kernel 3: FDS MLP + dynamic kernel.
// ============================================================================
__global__ void __launch_bounds__(256) k_mlp(
    const float* __restrict__ m1w, const float* __restrict__ m1b,
    const float* __restrict__ m2w, const float* __restrict__ m2b,
    const float* __restrict__ basis)
{
    int b = blockIdx.x;
    int tid = threadIdx.x;
    __shared__ float gs[MID];
    __shared__ float hid[24];
    __shared__ float wsm[4];

    if (tid < MID) gs[tid] = g_gvec[b * MID + tid];
    __syncthreads();
    if (tid < 24) {
        float a = m1b[tid];
        for (int c = 0; c < MID; c++) a = fmaf(gs[c], m1w[tid * MID + c], a);
        hid[tid] = fmaxf(a, 0.f);
    }
    __syncthreads();
    if (tid < 4) {
        float a = m2b[tid];
        for (int h = 0; h < 24; h++) a = fmaf(hid[h], m2w[tid * 24 + h], a);
        wsm[tid] = a;
    }
    __syncthreads();
    if (tid == 0) {
        float mx = fmaxf(fmaxf(wsm[0], wsm[1]), fmaxf(wsm[2], wsm[3]));
        float e0 = expf(wsm[0] - mx), e1 = expf(wsm[1] - mx);
        float e2 = expf(wsm[2] - mx), e3 = expf(wsm[3] - mx);
        float inv = 1.f / (e0 + e1 + e2 + e3);
        wsm[0] = e0 * inv; wsm[1] = e1 * inv; wsm[2] = e2 * inv; wsm[3] = e3 * inv;
    }
    __syncthreads();
    for (int i = tid; i < MID * NTAP; i += 256) {
        int c = i / NTAP, tj = i % NTAP;
        float v = 0.f;
        #pragma unroll
        for (int k = 0; k < 4; k++)
            v = fmaf(wsm[k], basis[(k * MID + c) * NTAP + tj], v);
        g_dyn[(b * NTAP + tj) * MID + c] = v;
    }
}

// ============================================================================
// Kernel 4: depthwise 3x3 conv + bias + SiLU.
// ============================================================================
__global__ void __launch_bounds__(256) k_dw(
    const float* __restrict__ dww, const float* __restrict__ dwb)
{
    int idx = blockIdx.x * 256 + threadIdx.x;
    int c4 = idx % 24;
    int p  = (idx / 24) & (HWP - 1);
    int b  = idx / (24 * HWP);
    int c  = c4 * 4;
    int i = p >> 6, j = p & 63;

    float4 acc = make_float4(0.f, 0.f, 0.f, 0.f);
    #pragma unroll
    for (int kh = 0; kh < 3; kh++) {
        int ni = i + kh - 1;
        if ((unsigned)ni >= 64u) continue;
        #pragma unroll
        for (int kw = 0; kw < 3; kw++) {
            int nj = j + kw - 1;
            if ((unsigned)nj >= 64u) continue;
            float4 v = *reinterpret_cast<const float4*>(
                &g_temb[((b * HWP) + (ni << 6) + nj) * MID + c]);
            int wo = kh * 3 + kw;
            acc.x = fmaf(v.x, dww[(c + 0) * 9 + wo], acc.x);
            acc.y = fmaf(v.y, dww[(c + 1) * 9 + wo], acc.y);
            acc.z = fmaf(v.z, dww[(c + 2) * 9 + wo], acc.z);
            acc.w = fmaf(v.w, dww[(c + 3) * 9 + wo], acc.w);
        }
    }
    acc.x += dwb[c + 0]; acc.y += dwb[c + 1];
    acc.z += dwb[c + 2]; acc.w += dwb[c + 3];
    acc.x = acc.x / (1.f + expf(-acc.x));
    acc.y = acc.y / (1.f + expf(-acc.y));
    acc.z = acc.z / (1.f + expf(-acc.z));
    acc.w = acc.w / (1.f + expf(-acc.w));
    *reinterpret_cast<float4*>(&g_y[(b * HWP + p) * MID + c]) = acc;
}

// ============================================================================
// Kernel 5: style 1x1 conv (96 -> 192) tf32 MMA fused with
// common = x_emb * (1 + gamma) + beta. Tile 128 x 192, 256 threads,
// 8 m-warps, warp tile 16 x 192 (24 n8 tiles: nt 0..11 gamma, 12..23 beta).
// ============================================================================
__global__ void __launch_bounds__(256) k_style(
    const float* __restrict__ pww, const float* __restrict__ pwb)
{
    __shared__ float As[128][36];
    __shared__ float Bs[192][36];

    const int tid = threadIdx.x;
    const int warp = tid >> 5, lane = tid & 31;
    const int gid = lane >> 2, ctid = lane & 3;
    const int base = blockIdx.x * 128;
    const int cS = tid & 31, rT = tid >> 5;

    float acc[24][4];
    #pragma unroll
    for (int j = 0; j < 24; j++)
        #pragma unroll
        for (int q = 0; q < 4; q++) acc[j][q] = 0.f;

    for (int k0 = 0; k0 < MID; k0 += 32) {
        #pragma unroll
        for (int rr = 0; rr < 16; rr++) {
            int r = rT + rr * 8;
            As[r][cS] = to_tf32(g_y[(base + r) * MID + k0 + cS]);
        }
        #pragma unroll
        for (int jj = 0; jj < 24; jj++) {
            int j = rT + jj * 8;
            Bs[j][cS] = to_tf32(pww[j * MID + k0 + cS]);
        }
        __syncthreads();
        #pragma unroll
        for (int ks = 0; ks < 4; ks++) {
            const int k8 = ks * 8;
            int r = warp * 16;
            uint32_t a[4];
            a[0] = __float_as_uint(As[r + gid    ][k8 + ctid]);
            a[1] = __float_as_uint(As[r + gid + 8][k8 + ctid]);
            a[2] = __float_as_uint(As[r + gid    ][k8 + ctid + 4]);
            a[3] = __float_as_uint(As[r + gid + 8][k8 + ctid + 4]);
            #pragma unroll
            for (int nt = 0; nt < 24; nt++) {
                int n = nt * 8;
                uint32_t b0 = __float_as_uint(Bs[n + gid][k8 + ctid]);
                uint32_t b1 = __float_as_uint(Bs[n + gid][k8 + ctid + 4]);
                MMA_TF32(acc[nt], a, b0, b1);
            }
        }
        __syncthreads();
    }

    // epilogue: gamma = acc[nt] (cols c), beta = acc[nt+12] (cols c+96)
    #pragma unroll
    for (int nt = 0; nt < 12; nt++) {
        int c = nt * 8 + 2 * ctid;
        float gb0 = pwb[c], gb1 = pwb[c + 1];
        float bb0 = pwb[MID + c], bb1 = pwb[MID + c + 1];
        int row0 = base + warp * 16 + gid;
        {
            float g0 = acc[nt][0] + gb0, g1 = acc[nt][1] + gb1;
            float b0 = acc[nt + 12][0] + bb0, b1 = acc[nt + 12][1] + bb1;
            float2 xe = *reinterpret_cast<const float2*>(&g_xemb[row0 * MID + c]);
            float2 o = make_float2(xe.x * (1.f + g0) + b0, xe.y * (1.f + g1) + b1);
            *reinterpret_cast<float2*>(&g_common[row0 * MID + c]) = o;
        }
        {
            int row1 = row0 + 8;
            float g0 = acc[nt][2] + gb0, g1 = acc[nt][3] + gb1;
            float b0 = acc[nt + 12][2] + bb0, b1 = acc[nt + 12][3] + bb1;
            float2 xe = *reinterpret_cast<const float2*>(&g_xemb[row1 * MID + c]);
            float2 o = make_float2(xe.x * (1.f + g0) + b0, xe.y * (1.f + g1) + b1);
            *reinterpret_cast<float2*>(&g_common[row1 * MID + c]) = o;
        }
    }
}

// ============================================================================
// Kernel 6: FDS 49-tap circular conv, smem-tiled.
// Block: (b, 8-channel group, 8-row band). 512 threads = 64 cols x 8 ch.
// Stage 14 rows x 64 cols x 8 ch; taps hoisted into registers.
// Output staged through smem for coalesced float4 stores.
// ============================================================================
__global__ void __launch_bounds__(512) k_fds()
{
    __shared__ float sm[14][8][65];
    __shared__ float dyn_s[NTAP * 8];
    __shared__ float out_s[8][8][65];

    const int bx = blockIdx.x;
    const int b  = bx / 96;
    const int rem = bx % 96;
    const int cg = rem / 8, rb = rem % 8;
    const int r0 = rb * 8, c0 = cg * 8;
    const int tid = threadIdx.x;
    const int ch = tid >> 6, col = tid & 63;

    if (tid < NTAP * 8) {
        int tap = tid >> 3, chl = tid & 7;
        dyn_s[tap * 8 + chl] = g_dyn[(b * NTAP + tap) * MID + c0 + chl];
    }
    for (int idx = tid; idx < 14 * 64 * 2; idx += 512) {
        int half = idx & 1, pos = idx >> 1;
        int rowI = pos >> 6, colI = pos & 63;
        int srow = (r0 - 3 + rowI) & 63;
        float4 v = *reinterpret_cast<const float4*>(
            &g_common[((b << 12) + (srow << 6) + colI) * MID + c0 + half * 4]);
        sm[rowI][half * 4 + 0][colI] = v.x;
        sm[rowI][half * 4 + 1][colI] = v.y;
        sm[rowI][half * 4 + 2][colI] = v.z;
        sm[rowI][half * 4 + 3][colI] = v.w;
    }
    __syncthreads();

    float kt[NTAP];
    #pragma unroll
    for (int i = 0; i < NTAP; i++) kt[i] = dyn_s[i * 8 + ch];

    #pragma unroll
    for (int rr = 0; rr < 8; rr++) {
        float acc = 0.f;
        #pragma unroll
        for (int ap = 0; ap < 7; ap++) {
            #pragma unroll
            for (int dp = 0; dp < 7; dp++) {
                int cc = (col + dp - 3) & 63;
                acc = fmaf(kt[(6 - ap) * 7 + (6 - dp)], sm[rr + ap][ch][cc], acc);
            }
        }
        out_s[rr][ch][col] = acc;
    }
    __syncthreads();

    for (int idx = tid; idx < 8 * 64 * 2; idx += 512) {
        int half = idx & 1, pos = idx >> 1;
        int rr = pos >> 6, colI = pos & 63;
        float4 v;
        v.x = out_s[rr][half * 4 + 0][colI];
        v.y = out_s[rr][half * 4 + 1][colI];
        v.z = out_s[rr][half * 4 + 2][colI];
        v.w = out_s[rr][half * 4 + 3][colI];
        *reinterpret_cast<float4*>(
            &g_fds[((b << 12) + ((r0 + rr) << 6) + colI) * MID + c0 + half * 4]) = v;
    }
}

// ============================================================================
// Kernel 7: up Linear (96 -> 768) tf32 MMA + bias + residual.
// Tile 128 x 128, grid.y = 6. 8 warps: 4m x 2n; warp tile 32 x 64.
// ============================================================================
__global__ void __launch_bounds__(256, 2) k_up(
    const float* __restrict__ upw, const float* __restrict__ upb,
    const float* __restrict__ x, float* __restrict__ out)
{
    __shared__ float As[128][36];
    __shared__ float Bs[128][36];

    const int tid = threadIdx.x;
    const int warp = tid >> 5, lane = tid & 31;
    const int gid = lane >> 2, ctid = lane & 3;
    const int wm = warp >> 1, wn = warp & 1;
    const int base = blockIdx.x * 128;
    const int n0   = blockIdx.y * 128;
    const int cS = tid & 31, rT = tid >> 5;

    float acc[2][8][4];
    #pragma unroll
    for (int i = 0; i < 2; i++)
        #pragma unroll
        for (int j = 0; j < 8; j++)
            #pragma unroll
            for (int q = 0; q < 4; q++) acc[i][j][q] = 0.f;

    for (int k0 = 0; k0 < MID; k0 += 32) {
        #pragma unroll
        for (int rr = 0; rr < 16; rr++) {
            int r = rT + rr * 8;
            As[r][cS] = to_tf32(g_fds[(base + r) * MID + k0 + cS]);
            Bs[r][cS] = to_tf32(upw[(n0 + r) * MID + k0 + cS]);
        }
        __syncthreads();
        #pragma unroll
        for (int ks = 0; ks < 4; ks++) {
            const int k8 = ks * 8;
            uint32_t a[2][4];
            #pragma unroll
            for (int mt = 0; mt < 2; mt++) {
                int r = wm * 32 + mt * 16;
                a[mt][0] = __float_as_uint(As[r + gid    ][k8 + ctid]);
                a[mt][1] = __float_as_uint(As[r + gid + 8][k8 + ctid]);
                a[mt][2] = __float_as_uint(As[r + gid    ][k8 + ctid + 4]);
                a[mt][3] = __float_as_uint(As[r + gid + 8][k8 + ctid + 4]);
            }
            #pragma unroll
            for (int nt = 0; nt < 8; nt++) {
                int n = wn * 64 + nt * 8;
                uint32_t b0 = __float_as_uint(Bs[n + gid][k8 + ctid]);
                uint32_t b1 = __float_as_uint(Bs[n + gid][k8 + ctid + 4]);
                MMA_TF32(acc[0][nt], a[0], b0, b1);
                MMA_TF32(acc[1][nt], a[1], b0, b1);
            }
        }
        __syncthreads();
    }

    #pragma unroll
    for (int mt = 0; mt < 2; mt++) {
        int row0 = base + wm * 32 + mt * 16 + gid;
        #pragma unroll
        for (int nt = 0; nt < 8; nt++) {
            int c = n0 + wn * 64 + nt * 8 + 2 * ctid;
            float2 bb = *reinterpret_cast<const float2*>(&upb[c]);
            {
                float2 xr = *reinterpret_cast<const float2*>(&x[row0 * DIM + c]);
                float2 o = make_float2(acc[mt][nt][0] + bb.x + xr.x,
                                       acc[mt][nt][1] + bb.y + xr.y);
                *reinterpret_cast<float2*>(&out[row0 * DIM + c]) = o;
            }
            {
                int row1 = row0 + 8;
                float2 xr = *reinterpret_cast<const float2*>(&x[row1 * DIM + c]);
                float2 o = make_float2(acc[mt][nt][2] + bb.x + xr.x,
                                       acc[mt][nt][3] + bb.y + xr.y);
                *reinterpret_cast<float2*>(&out[row1 * DIM + c]) = o;
            }
        }
    }
}

// ============================================================================
extern "C" void kernel_launch(void* const* d_in, const int* in_sizes, int n_in,
                              void* d_out, int out_size)
{
    const float* x       = (const float*)d_in[0];
    const float* t       = (const float*)d_in[1];
    const float* ln_w    = (const float*)d_in[2];
    const float* ln_b    = (const float*)d_in[3];
    const float* down_w  = (const float*)d_in[4];
    const float* down_b  = (const float*)d_in[5];
    const float* ln1_w   = (const float*)d_in[6];
    const float* ln1_b   = (const float*)d_in[7];
    const float* down1_w = (const float*)d_in[8];
    const float* down1_b = (const float*)d_in[9];
    const float* dw_w    = (const float*)d_in[10];
    const float* dw_b    = (const float*)d_in[11];
    const float* pw_w    = (const float*)d_in[12];
    const float* pw_b    = (const float*)d_in[13];
    const float* mlp1_w  = (const float*)d_in[14];
    const float* mlp1_b  = (const float*)d_in[15];
    const float* mlp2_w  = (const float*)d_in[16];
    const float* mlp2_b  = (const float*)d_in[17];
    const float* basis   = (const float*)d_in[18];
    const float* up_w    = (const float*)d_in[19];
    const float* up_b    = (const float*)d_in[20];
    float* out = (float*)d_out;

    k_ln_down<<<dim3(NPIX / 128, 2), 256>>>(x, t, ln_w, ln_b, down_w, down_b,
                                            ln1_w, ln1_b, down1_w, down1_b);
    k_gvec<<<NB, 384>>>();
    k_mlp<<<NB, 256>>>(mlp1_w, mlp1_b, mlp2_w, mlp2_b, basis);
    k_dw<<<NPIX * 24 / 256, 256>>>(dw_w, dw_b);
    k_style<<<NPIX / 128, 256>>>(pw_w, pw_b);
    k_fds<<<NB * 96, 512>>>();
    k_up<<<dim3(NPIX / 128, DIM / 128), 256>>>(up_w, up_b, x, out);
}